// round 2
// baseline (speedup 1.0000x reference)
#include <cuda_runtime.h>
#include <cuda_bf16.h>

// Problem shape (fixed by the dataset)
#define NPTS   4096     // coarse points (x, pos, batch)
#define NS     16384    // fine points (x_skip, pos_skip, batch_skip)
#define CH     256      // coarse feature channels
#define CSKIP  128      // skip feature channels
#define DIN    384      // CH + CSKIP
#define HID    256      // hidden dim
#define BMAX   8        // upper bound on batch count

// Scratch (static device globals; no allocation allowed)
__device__ float g_y[NS * DIN];     // interpolated + concat features
__device__ float g_h[NS * HID];     // hidden activations
__device__ int   g_idx[NS * 3];
__device__ float g_w[NS * 3];       // normalized weights
__device__ int   g_bstart[BMAX + 1];

// ---------------------------------------------------------------------------
// 1) batch segment boundaries (batch is sorted)
// ---------------------------------------------------------------------------
__global__ void seg_kernel(const int* __restrict__ batch, int n) {
    int j = blockIdx.x * blockDim.x + threadIdx.x;
    if (j >= n) return;
    int b  = batch[j];
    int bp = (j == 0) ? -1 : batch[j - 1];
    for (int v = bp + 1; v <= b; v++) g_bstart[v] = j;
    if (j == n - 1) {
        for (int v = b + 1; v <= BMAX; v++) g_bstart[v] = n;
    }
}

// ---------------------------------------------------------------------------
// 2) kNN (K=3) per fine point, restricted to its batch segment.
//    Coarse points packed (x,y,z,batch) in dynamic smem as float4.
// ---------------------------------------------------------------------------
__global__ void knn_kernel(const float* __restrict__ pos,
                           const int* __restrict__ batch,
                           const float* __restrict__ pos_skip,
                           const int* __restrict__ batch_skip) {
    extern __shared__ float4 s_pts[];   // NPTS float4 = 64 KB
    int tid = threadIdx.x;
    for (int j = tid; j < NPTS; j += blockDim.x) {
        float4 p;
        p.x = pos[3 * j + 0];
        p.y = pos[3 * j + 1];
        p.z = pos[3 * j + 2];
        p.w = 0.0f;
        s_pts[j] = p;
    }
    __syncthreads();

    int t = blockIdx.x * blockDim.x + tid;
    if (t >= NS) return;

    float qx = pos_skip[3 * t + 0];
    float qy = pos_skip[3 * t + 1];
    float qz = pos_skip[3 * t + 2];
    int   qb = batch_skip[t];
    int j0 = g_bstart[qb];
    int j1 = g_bstart[qb + 1];

    float b0 = 3.0e38f, b1 = 3.0e38f, b2 = 3.0e38f;
    int   i0 = j0, i1 = j0, i2 = j0;

    for (int j = j0; j < j1; j++) {
        float4 p = s_pts[j];
        float dx = p.x - qx;
        float dy = p.y - qy;
        float dz = p.z - qz;
        float d = fmaf(dx, dx, fmaf(dy, dy, dz * dz));
        // strict < keeps earliest index on ties, matching lax.top_k
        if (d < b2) {
            if (d < b1) {
                if (d < b0) {
                    b2 = b1; i2 = i1; b1 = b0; i1 = i0; b0 = d; i0 = j;
                } else {
                    b2 = b1; i2 = i1; b1 = d; i1 = j;
                }
            } else {
                b2 = d; i2 = j;
            }
        }
    }

    float w0 = 1.0f / fmaxf(b0, 1e-16f);
    float w1 = 1.0f / fmaxf(b1, 1e-16f);
    float w2 = 1.0f / fmaxf(b2, 1e-16f);
    float inv = 1.0f / (w0 + w1 + w2);
    g_w[3 * t + 0] = w0 * inv;
    g_w[3 * t + 1] = w1 * inv;
    g_w[3 * t + 2] = w2 * inv;
    g_idx[3 * t + 0] = i0;
    g_idx[3 * t + 1] = i1;
    g_idx[3 * t + 2] = i2;
}

// ---------------------------------------------------------------------------
// 3) weighted gather of 3 coarse rows + concat skip features -> g_y[NS, DIN]
//    one block (128 threads) per fine point; coalesced row reads
// ---------------------------------------------------------------------------
__global__ void interp_kernel(const float* __restrict__ x,
                              const float* __restrict__ x_skip) {
    int t = blockIdx.x;
    int c = threadIdx.x;             // 0..127
    int   i0 = g_idx[3 * t + 0], i1 = g_idx[3 * t + 1], i2 = g_idx[3 * t + 2];
    float w0 = g_w[3 * t + 0],  w1 = g_w[3 * t + 1],  w2 = g_w[3 * t + 2];
    float* yrow = g_y + (size_t)t * DIN;
    const float* r0 = x + (size_t)i0 * CH;
    const float* r1 = x + (size_t)i1 * CH;
    const float* r2 = x + (size_t)i2 * CH;
    #pragma unroll
    for (int cc = c; cc < CH; cc += 128) {
        yrow[cc] = w0 * r0[cc] + w1 * r1[cc] + w2 * r2[cc];
    }
    yrow[CH + c] = x_skip[(size_t)t * CSKIP + c];
}

// ---------------------------------------------------------------------------
// 4) GEMM + bias + ReLU: C[M,N] = relu(A[M,K] @ B[K,N] + bias[N])
//    64x64 tile, BK=16, 256 threads, 4x4 microtile per thread
// ---------------------------------------------------------------------------
__global__ void __launch_bounds__(256)
gemm_bias_relu(const float* __restrict__ A, const float* __restrict__ B,
               const float* __restrict__ bias, float* __restrict__ Cout,
               int M, int N, int K) {
    __shared__ float As[16][64];   // transposed A tile: As[k][m]
    __shared__ float Bs[16][64];

    int tid = threadIdx.x;
    int bx = blockIdx.x;           // N tile
    int by = blockIdx.y;           // M tile

    const float* Ab = A + (size_t)by * 64 * K;
    const float* Bb = B + bx * 64;

    // A-load mapping: each thread 1x float4
    int la_r = tid >> 2;           // 0..63 (row within tile)
    int la_k = (tid & 3) * 4;      // k offset
    // B-load mapping
    int lb_k = tid >> 4;           // 0..15
    int lb_n = (tid & 15) * 4;

    int tx = (tid & 15) * 4;       // col micro-tile origin
    int ty = (tid >> 4) * 4;       // row micro-tile origin

    float acc[4][4];
    #pragma unroll
    for (int i = 0; i < 4; i++)
        #pragma unroll
        for (int j = 0; j < 4; j++) acc[i][j] = 0.0f;

    for (int k0 = 0; k0 < K; k0 += 16) {
        float4 av = *(const float4*)(Ab + (size_t)la_r * K + k0 + la_k);
        float4 bv = *(const float4*)(Bb + (size_t)(k0 + lb_k) * N + lb_n);
        As[la_k + 0][la_r] = av.x;
        As[la_k + 1][la_r] = av.y;
        As[la_k + 2][la_r] = av.z;
        As[la_k + 3][la_r] = av.w;
        *(float4*)&Bs[lb_k][lb_n] = bv;
        __syncthreads();

        #pragma unroll
        for (int kk = 0; kk < 16; kk++) {
            float4 a = *(const float4*)&As[kk][ty];
            float4 b = *(const float4*)&Bs[kk][tx];
            acc[0][0] = fmaf(a.x, b.x, acc[0][0]);
            acc[0][1] = fmaf(a.x, b.y, acc[0][1]);
            acc[0][2] = fmaf(a.x, b.z, acc[0][2]);
            acc[0][3] = fmaf(a.x, b.w, acc[0][3]);
            acc[1][0] = fmaf(a.y, b.x, acc[1][0]);
            acc[1][1] = fmaf(a.y, b.y, acc[1][1]);
            acc[1][2] = fmaf(a.y, b.z, acc[1][2]);
            acc[1][3] = fmaf(a.y, b.w, acc[1][3]);
            acc[2][0] = fmaf(a.z, b.x, acc[2][0]);
            acc[2][1] = fmaf(a.z, b.y, acc[2][1]);
            acc[2][2] = fmaf(a.z, b.z, acc[2][2]);
            acc[2][3] = fmaf(a.z, b.w, acc[2][3]);
            acc[3][0] = fmaf(a.w, b.x, acc[3][0]);
            acc[3][1] = fmaf(a.w, b.y, acc[3][1]);
            acc[3][2] = fmaf(a.w, b.z, acc[3][2]);
            acc[3][3] = fmaf(a.w, b.w, acc[3][3]);
        }
        __syncthreads();
    }

    #pragma unroll
    for (int j = 0; j < 4; j++) {
        float bv = bias[bx * 64 + tx + j];
        #pragma unroll
        for (int i = 0; i < 4; i++) {
            float v = acc[i][j] + bv;
            v = fmaxf(v, 0.0f);
            Cout[(size_t)(by * 64 + ty + i) * N + bx * 64 + tx + j] = v;
        }
    }
}

// ---------------------------------------------------------------------------
// 5) tail outputs: pos_skip (float) and batch_skip (cast to float)
// ---------------------------------------------------------------------------
__global__ void tail_kernel(const float* __restrict__ pos_skip,
                            const int* __restrict__ batch_skip,
                            float* __restrict__ out, int write_batch) {
    int i = blockIdx.x * blockDim.x + threadIdx.x;
    if (i < NS * 3) out[(size_t)NS * HID + i] = pos_skip[i];
    if (write_batch && i < NS)
        out[(size_t)NS * HID + (size_t)NS * 3 + i] = (float)batch_skip[i];
}

// ---------------------------------------------------------------------------
extern "C" void kernel_launch(void* const* d_in, const int* in_sizes, int n_in,
                              void* d_out, int out_size) {
    const float* x          = (const float*)d_in[0];
    const float* pos        = (const float*)d_in[1];
    const int*   batch      = (const int*)  d_in[2];
    const float* x_skip     = (const float*)d_in[3];
    const float* pos_skip   = (const float*)d_in[4];
    const int*   batch_skip = (const int*)  d_in[5];
    const float* W1         = (const float*)d_in[6];
    const float* b1         = (const float*)d_in[7];
    const float* W2         = (const float*)d_in[8];
    const float* b2         = (const float*)d_in[9];
    float* out = (float*)d_out;

    float* p_y; float* p_h;
    cudaGetSymbolAddress((void**)&p_y, g_y);
    cudaGetSymbolAddress((void**)&p_h, g_h);

    // 1) batch segments
    seg_kernel<<<(NPTS + 255) / 256, 256>>>(batch, NPTS);

    // 2) kNN (64 KB dynamic smem)
    static bool attr_set = false;
    size_t smem = (size_t)NPTS * sizeof(float4);
    cudaFuncSetAttribute(knn_kernel, cudaFuncAttributeMaxDynamicSharedMemorySize,
                         (int)smem);
    knn_kernel<<<NS / 128, 128, smem>>>(pos, batch, pos_skip, batch_skip);

    // 3) interpolate + concat
    interp_kernel<<<NS, 128>>>(x, x_skip);

    // 4) MLP
    {
        dim3 grid(HID / 64, NS / 64);
        gemm_bias_relu<<<grid, 256>>>(p_y, W1, b1, p_h, NS, HID, DIN);
    }
    {
        dim3 grid(HID / 64, NS / 64);
        gemm_bias_relu<<<grid, 256>>>(p_h, W2, b2, out, NS, HID, HID);
    }

    // 5) tuple tail (pos_skip, batch_skip) if the output buffer includes it
    long long need_pos   = (long long)NS * HID + (long long)NS * 3;
    long long need_batch = need_pos + NS;
    if ((long long)out_size >= need_pos) {
        int wb = ((long long)out_size >= need_batch) ? 1 : 0;
        tail_kernel<<<(NS * 3 + 255) / 256, 256>>>(pos_skip, batch_skip, out, wb);
    }
    (void)attr_set; (void)n_in; (void)in_sizes;
}

// round 4
// speedup vs baseline: 1.9861x; 1.9861x over previous
#include <cuda_runtime.h>
#include <cuda_bf16.h>
#include <cstdint>

// Problem shape (fixed by the dataset)
#define NPTS   4096
#define NS     16384
#define CH     256
#define CSKIP  128
#define DIN    384
#define HID    256
#define BMAX   8

// GEMM tiling
#define BM 128
#define BN 128
#define BK 32
#define SMS 36              // smem row stride (floats): conflict-free frag loads
#define STAGE (BM * SMS)    // 4608 floats per operand per stage

// Scratch (static device globals; no allocation allowed)
__device__ float g_h[NS * HID];        // hidden activations (tf32-rounded)
__device__ float g_w1t[HID * DIN];     // W1^T  [N=256, K=384], tf32-rounded
__device__ float g_w2t[HID * HID];     // W2^T  [N=256, K=256], tf32-rounded
__device__ int   g_idx[NS * 3];
__device__ float g_w[NS * 3];
__device__ int   g_bstart[BMAX + 1];

// ===========================================================================
// helpers
// ===========================================================================
__device__ __forceinline__ uint32_t smem_u32(const void* p) {
    uint32_t a;
    asm("{ .reg .u64 t; cvta.to.shared.u64 t, %1; cvt.u32.u64 %0, t; }"
        : "=r"(a) : "l"(p));
    return a;
}
__device__ __forceinline__ uint32_t to_tf32(float f) {
    uint32_t u;
    asm("cvt.rna.tf32.f32 %0, %1;" : "=r"(u) : "f"(f));
    return u;
}
__device__ __forceinline__ float tf32f(float f) {
    return __uint_as_float(to_tf32(f));
}
__device__ __forceinline__ void cp16(uint32_t sdst, const void* gsrc) {
    asm volatile("cp.async.ca.shared.global [%0], [%1], 16;"
                 :: "r"(sdst), "l"(gsrc));
}
#define CP_COMMIT() asm volatile("cp.async.commit_group;" ::: "memory")
#define CP_WAIT0()  asm volatile("cp.async.wait_group 0;"  ::: "memory")

__device__ __forceinline__ void mma_tf32(float c[4], const uint32_t a[4],
                                         const uint32_t b[2]) {
    asm volatile(
        "mma.sync.aligned.m16n8k8.row.col.f32.tf32.tf32.f32 "
        "{%0,%1,%2,%3}, {%4,%5,%6,%7}, {%8,%9}, {%0,%1,%2,%3};"
        : "+f"(c[0]), "+f"(c[1]), "+f"(c[2]), "+f"(c[3])
        : "r"(a[0]), "r"(a[1]), "r"(a[2]), "r"(a[3]), "r"(b[0]), "r"(b[1]));
}

// ===========================================================================
// 1) batch segment boundaries (batch is sorted)
// ===========================================================================
__global__ void seg_kernel(const int* __restrict__ batch, int n) {
    int j = blockIdx.x * blockDim.x + threadIdx.x;
    if (j >= n) return;
    int b  = batch[j];
    int bp = (j == 0) ? -1 : batch[j - 1];
    for (int v = bp + 1; v <= b; v++) g_bstart[v] = j;
    if (j == n - 1) {
        for (int v = b + 1; v <= BMAX; v++) g_bstart[v] = n;
    }
}

// ===========================================================================
// 2) kNN (K=3) per fine point, restricted to its batch segment
// ===========================================================================
__global__ void knn_kernel(const float* __restrict__ pos,
                           const float* __restrict__ pos_skip,
                           const int* __restrict__ batch_skip) {
    extern __shared__ float4 s_pts[];
    int tid = threadIdx.x;
    for (int j = tid; j < NPTS; j += blockDim.x) {
        float4 p;
        p.x = pos[3 * j + 0];
        p.y = pos[3 * j + 1];
        p.z = pos[3 * j + 2];
        p.w = 0.0f;
        s_pts[j] = p;
    }
    __syncthreads();

    int t = blockIdx.x * blockDim.x + tid;
    float qx = pos_skip[3 * t + 0];
    float qy = pos_skip[3 * t + 1];
    float qz = pos_skip[3 * t + 2];
    int   qb = batch_skip[t];
    int j0 = g_bstart[qb];
    int j1 = g_bstart[qb + 1];

    float b0 = 3.0e38f, b1 = 3.0e38f, b2 = 3.0e38f;
    int   i0 = j0, i1 = j0, i2 = j0;

    #pragma unroll 4
    for (int j = j0; j < j1; j++) {
        float4 p = s_pts[j];
        float dx = p.x - qx;
        float dy = p.y - qy;
        float dz = p.z - qz;
        float d = fmaf(dx, dx, fmaf(dy, dy, dz * dz));
        if (d < b2) {
            if (d < b1) {
                if (d < b0) {
                    b2 = b1; i2 = i1; b1 = b0; i1 = i0; b0 = d; i0 = j;
                } else {
                    b2 = b1; i2 = i1; b1 = d; i1 = j;
                }
            } else {
                b2 = d; i2 = j;
            }
        }
    }

    float w0 = 1.0f / fmaxf(b0, 1e-16f);
    float w1 = 1.0f / fmaxf(b1, 1e-16f);
    float w2 = 1.0f / fmaxf(b2, 1e-16f);
    float inv = 1.0f / (w0 + w1 + w2);
    g_w[3 * t + 0] = w0 * inv;
    g_w[3 * t + 1] = w1 * inv;
    g_w[3 * t + 2] = w2 * inv;
    g_idx[3 * t + 0] = i0;
    g_idx[3 * t + 1] = i1;
    g_idx[3 * t + 2] = i2;
}

// ===========================================================================
// 3) weight transpose + tf32 pre-round:  W[K,N] -> Wt[N,K]
// ===========================================================================
__global__ void transpose_w(const float* __restrict__ W, float* __restrict__ Wt,
                            int K, int N) {
    __shared__ float tile[32][33];
    int k0 = blockIdx.x * 32, n0 = blockIdx.y * 32;
    int tx = threadIdx.x, ty = threadIdx.y;
    for (int i = ty; i < 32; i += 8)
        tile[i][tx] = W[(size_t)(k0 + i) * N + n0 + tx];
    __syncthreads();
    for (int i = ty; i < 32; i += 8)
        Wt[(size_t)(n0 + i) * K + k0 + tx] = tf32f(tile[tx][i]);
}

// ===========================================================================
// 4) mma.sync tf32 GEMM + bias + ReLU.
//    C[M, 256] = relu(A[M,K] @ Wt^T + bias)
//    FUSED: A row m built on the fly = [knn-interp(x), x_skip] (tf32-rounded)
//    EPI_TF32: round the output to tf32 (it feeds the next GEMM)
// ===========================================================================
template<int KTOT, bool FUSED, bool EPI_TF32>
__global__ void __launch_bounds__(256, 2)
gemm_mma(const float* __restrict__ A,
         const float* __restrict__ x,
         const float* __restrict__ xs,
         const float* __restrict__ Wt,
         const float* __restrict__ bias,
         float* __restrict__ C) {
    extern __shared__ float smem[];
    float* sA = smem;                 // [2][BM*SMS]
    float* sB = smem + 2 * STAGE;     // [2][BN*SMS]

    const int tid  = threadIdx.x;
    const int wid  = tid >> 5, lane = tid & 31;
    const int gid  = lane >> 2, tg = lane & 3;
    const int wm0  = (wid & 3) * 32;      // warp M origin (4 warps along M)
    const int wn0  = (wid >> 2) * 64;     // warp N origin (2 warps along N)
    const int m0   = blockIdx.x * BM;
    const int n0   = blockIdx.y * BN;

    const int arow  = tid >> 1;           // 0..127 (row this thread loads)
    const int akoff = (tid & 1) * 16;     // half-row k offset (floats)

    int i0 = 0, i1 = 0, i2 = 0;
    float w0 = 0, w1 = 0, w2 = 0;
    if (FUSED) {
        int m = m0 + arow;
        i0 = g_idx[3 * m]; i1 = g_idx[3 * m + 1]; i2 = g_idx[3 * m + 2];
        w0 = g_w[3 * m];   w1 = g_w[3 * m + 1];   w2 = g_w[3 * m + 2];
    }

    float acc[2][8][4];
    #pragma unroll
    for (int mt = 0; mt < 2; mt++)
        #pragma unroll
        for (int nt = 0; nt < 8; nt++)
            #pragma unroll
            for (int q = 0; q < 4; q++) acc[mt][nt][q] = 0.0f;

    constexpr int T = KTOT / BK;

    auto issue = [&](int t) {
        int s  = t & 1;
        int k0 = t * BK;
        float* dA = sA + s * STAGE;
        float* dB = sB + s * STAGE;
        // B tile: Wt rows n0+arow, k k0+akoff.. (+16 floats)
        {
            const float* src = Wt + (size_t)(n0 + arow) * KTOT + k0 + akoff;
            uint32_t dst = smem_u32(dB + arow * SMS + akoff);
            #pragma unroll
            for (int j = 0; j < 4; j++) cp16(dst + j * 16, src + j * 4);
        }
        // A tile
        if (FUSED) {
            #pragma unroll
            for (int j = 0; j < 4; j++) {
                int kk = akoff + j * 4;
                int kg = k0 + kk;
                float4 v;
                if (kg < CH) {
                    float4 a0 = *(const float4*)(x + (size_t)i0 * CH + kg);
                    float4 a1 = *(const float4*)(x + (size_t)i1 * CH + kg);
                    float4 a2 = *(const float4*)(x + (size_t)i2 * CH + kg);
                    v.x = w0 * a0.x + w1 * a1.x + w2 * a2.x;
                    v.y = w0 * a0.y + w1 * a1.y + w2 * a2.y;
                    v.z = w0 * a0.z + w1 * a1.z + w2 * a2.z;
                    v.w = w0 * a0.w + w1 * a1.w + w2 * a2.w;
                } else {
                    v = *(const float4*)(xs + (size_t)(m0 + arow) * CSKIP + (kg - CH));
                }
                uint4 u;
                u.x = to_tf32(v.x); u.y = to_tf32(v.y);
                u.z = to_tf32(v.z); u.w = to_tf32(v.w);
                *(uint4*)(dA + arow * SMS + kk) = u;
            }
        } else {
            const float* src = A + (size_t)(m0 + arow) * KTOT + k0 + akoff;
            uint32_t dst = smem_u32(dA + arow * SMS + akoff);
            #pragma unroll
            for (int j = 0; j < 4; j++) cp16(dst + j * 16, src + j * 4);
        }
    };

    issue(0);
    CP_COMMIT();

    for (int t = 0; t < T; t++) {
        CP_WAIT0();
        __syncthreads();
        if (t + 1 < T) { issue(t + 1); CP_COMMIT(); }

        int s = t & 1;
        const float* aA = sA + s * STAGE + wm0 * SMS;
        const float* aB = sB + s * STAGE + wn0 * SMS;

        #pragma unroll
        for (int ks = 0; ks < 4; ks++) {
            uint32_t af[2][4], bf[8][2];
            #pragma unroll
            for (int mt = 0; mt < 2; mt++) {
                const float* r = aA + (mt * 16 + gid) * SMS + ks * 8;
                af[mt][0] = __float_as_uint(r[tg]);
                af[mt][1] = __float_as_uint(r[8 * SMS + tg]);
                af[mt][2] = __float_as_uint(r[tg + 4]);
                af[mt][3] = __float_as_uint(r[8 * SMS + tg + 4]);
            }
            #pragma unroll
            for (int nt = 0; nt < 8; nt++) {
                const float* c = aB + (nt * 8 + gid) * SMS + ks * 8;
                bf[nt][0] = __float_as_uint(c[tg]);
                bf[nt][1] = __float_as_uint(c[tg + 4]);
            }
            #pragma unroll
            for (int mt = 0; mt < 2; mt++)
                #pragma unroll
                for (int nt = 0; nt < 8; nt++)
                    mma_tf32(acc[mt][nt], af[mt], bf[nt]);
        }
    }

    // epilogue: bias + relu (+ optional tf32 round), direct global stores
    #pragma unroll
    for (int mt = 0; mt < 2; mt++) {
        int r0 = m0 + wm0 + mt * 16 + gid;
        #pragma unroll
        for (int nt = 0; nt < 8; nt++) {
            int col = n0 + wn0 + nt * 8 + tg * 2;
            float bv0 = __ldg(bias + col);
            float bv1 = __ldg(bias + col + 1);
            float v0 = fmaxf(acc[mt][nt][0] + bv0, 0.0f);
            float v1 = fmaxf(acc[mt][nt][1] + bv1, 0.0f);
            float v2 = fmaxf(acc[mt][nt][2] + bv0, 0.0f);
            float v3 = fmaxf(acc[mt][nt][3] + bv1, 0.0f);
            if (EPI_TF32) {
                v0 = tf32f(v0); v1 = tf32f(v1); v2 = tf32f(v2); v3 = tf32f(v3);
            }
            *(float2*)(C + (size_t)r0 * 256 + col)       = make_float2(v0, v1);
            *(float2*)(C + (size_t)(r0 + 8) * 256 + col) = make_float2(v2, v3);
        }
    }
}

// ===========================================================================
// 5) tuple tail: pos_skip + batch_skip (as float)
// ===========================================================================
__global__ void tail_kernel(const float* __restrict__ pos_skip,
                            const int* __restrict__ batch_skip,
                            float* __restrict__ out, int write_batch) {
    int i = blockIdx.x * blockDim.x + threadIdx.x;
    if (i < NS * 3) out[(size_t)NS * HID + i] = pos_skip[i];
    if (write_batch && i < NS)
        out[(size_t)NS * HID + (size_t)NS * 3 + i] = (float)batch_skip[i];
}

// ===========================================================================
extern "C" void kernel_launch(void* const* d_in, const int* in_sizes, int n_in,
                              void* d_out, int out_size) {
    const float* x          = (const float*)d_in[0];
    const float* pos        = (const float*)d_in[1];
    const int*   batch      = (const int*)  d_in[2];
    const float* x_skip     = (const float*)d_in[3];
    const float* pos_skip   = (const float*)d_in[4];
    const int*   batch_skip = (const int*)  d_in[5];
    const float* W1         = (const float*)d_in[6];
    const float* b1         = (const float*)d_in[7];
    const float* W2         = (const float*)d_in[8];
    const float* b2         = (const float*)d_in[9];
    float* out = (float*)d_out;

    float *p_h, *p_w1t, *p_w2t;
    cudaGetSymbolAddress((void**)&p_h,   g_h);
    cudaGetSymbolAddress((void**)&p_w1t, g_w1t);
    cudaGetSymbolAddress((void**)&p_w2t, g_w2t);

    // 1) batch segments
    seg_kernel<<<(NPTS + 255) / 256, 256>>>(batch, NPTS);

    // 2) kNN
    size_t knn_smem = (size_t)NPTS * sizeof(float4);
    cudaFuncSetAttribute(knn_kernel, cudaFuncAttributeMaxDynamicSharedMemorySize,
                         (int)knn_smem);
    knn_kernel<<<NS / 128, 128, knn_smem>>>(pos, pos_skip, batch_skip);

    // 3) weight transposes (+ tf32 round)
    {
        dim3 b(32, 8);
        transpose_w<<<dim3(DIN / 32, HID / 32), b>>>(W1, p_w1t, DIN, HID);
        transpose_w<<<dim3(HID / 32, HID / 32), b>>>(W2, p_w2t, HID, HID);
    }

    // 4) MLP on tensor cores (mma.sync tf32); GEMM1 fuses interpolate+concat
    size_t gsmem = 4 * STAGE * sizeof(float);   // 73728 B
    cudaFuncSetAttribute(gemm_mma<DIN, true, true>,
                         cudaFuncAttributeMaxDynamicSharedMemorySize, (int)gsmem);
    cudaFuncSetAttribute(gemm_mma<HID, false, false>,
                         cudaFuncAttributeMaxDynamicSharedMemorySize, (int)gsmem);
    {
        dim3 grid(NS / BM, HID / BN);
        gemm_mma<DIN, true, true><<<grid, 256, gsmem>>>(
            nullptr, x, x_skip, p_w1t, b1, p_h);
        gemm_mma<HID, false, false><<<grid, 256, gsmem>>>(
            p_h, nullptr, nullptr, p_w2t, b2, out);
    }

    // 5) tuple tail
    long long need_pos   = (long long)NS * HID + (long long)NS * 3;
    long long need_batch = need_pos + NS;
    if ((long long)out_size >= need_pos) {
        int wb = ((long long)out_size >= need_batch) ? 1 : 0;
        tail_kernel<<<(NS * 3 + 255) / 256, 256>>>(pos_skip, batch_skip, out, wb);
    }
    (void)n_in; (void)in_sizes;
}